// round 6
// baseline (speedup 1.0000x reference)
#include <cuda_runtime.h>

#define BB 4096
#define FF 256
#define TT 128
#define DD 6
#define UU 16
#define NBIN 64

#define ROWS 32
#define LANES 8           /* trees per CTA = warps per CTA */
#define THREADS 256
#define TSPLIT 16
#define TPB (TT / TSPLIT) /* 8 trees per block: ONE tree-group, no loop */
#define XSTRIDE 260       /* 256+4 pad: conflict-free quarter-wavefront LDS.128 */
#define REDSTR 17         /* padded stride for per-warp reduction slab */

typedef unsigned long long u64t;

// ---- packed f32x2 helpers (sm_103a FFMA2 path, PTX-only per SASS_QUICKREF) ----
__device__ __forceinline__ u64t ffma2(u64t a, u64t b, u64t c) {
    u64t d;
    asm("fma.rn.f32x2 %0, %1, %2, %3;" : "=l"(d) : "l"(a), "l"(b), "l"(c));
    return d;
}
__device__ __forceinline__ u64t fmul2(u64t a, u64t b) {
    u64t d;
    asm("mul.rn.f32x2 %0, %1, %2;" : "=l"(d) : "l"(a), "l"(b));
    return d;
}
__device__ __forceinline__ u64t pk2(float lo, float hi) {
    u64t p;
    asm("mov.b64 %0, {%1, %2};" : "=l"(p) : "f"(lo), "f"(hi));
    return p;
}
__device__ __forceinline__ float2 unpk2(u64t p) {
    float2 v;
    asm("mov.b64 {%0, %1}, %2;" : "=f"(v.x), "=f"(v.y) : "l"(p));
    return v;
}

// Scratch (device globals: no runtime allocation allowed)
__device__ __align__(16) float g_selW[TT * DD * FF];   // [t][d][f], sparsemax-ed selectors
__device__ __align__(16) float g_a[TT * DD];           // 0.5*exp(-lt)
__device__ __align__(16) float g_b[TT * DD];           // 0.5 - th*a

// ---------------------------------------------------------------------------
// Prep: sparsemax over D=6 per (f,t); also the per-(t,d) affine for sparsemoid
// ---------------------------------------------------------------------------
__global__ void prep_kernel(const float* __restrict__ fsl,
                            const float* __restrict__ th,
                            const float* __restrict__ lt)
{
    int n = blockIdx.x * blockDim.x + threadIdx.x;

    if (n < TT * DD) {
        float a = 0.5f * expf(-lt[n]);
        g_a[n] = a;
        g_b[n] = 0.5f - th[n] * a;
    }
    if (n >= FF * TT) return;

    int f = n / TT;
    int t = n - f * TT;

    const float* zp = fsl + (size_t)f * (TT * DD) + t * DD;
    float z[DD], zs[DD];
#pragma unroll
    for (int d = 0; d < DD; ++d) { z[d] = zp[d]; zs[d] = z[d]; }

    // descending bubble sorting network (15 comparators, D=6)
#pragma unroll
    for (int p = 0; p < DD - 1; ++p) {
#pragma unroll
        for (int i = 0; i < DD - 1 - p; ++i) {
            float mx = fmaxf(zs[i], zs[i + 1]);
            float mn = fminf(zs[i], zs[i + 1]);
            zs[i] = mx; zs[i + 1] = mn;
        }
    }

    // sparsemax threshold
    float cs = 0.f, css = 0.f;
    int kz = 0;
#pragma unroll
    for (int k = 1; k <= DD; ++k) {
        cs += zs[k - 1];
        if (1.0f + (float)k * zs[k - 1] > cs) { kz = k; css = cs; }
    }
    float tau = (css - 1.0f) / (float)kz;

#pragma unroll
    for (int d = 0; d < DD; ++d)
        g_selW[(size_t)(t * DD + d) * FF + f] = fmaxf(z[d] - tau, 0.0f);
}

// ---------------------------------------------------------------------------
// Fused main kernel. block = 32 rows x 8 trees; warp <-> tree, lane <-> row.
// 2 CTAs/SM (smem ~100KB, regs capped 128). resp read via uniform LDG (L1D).
// ---------------------------------------------------------------------------
__global__ void __launch_bounds__(THREADS, 2)
main_kernel(const float* __restrict__ x,
            const float* __restrict__ resp,
            float* __restrict__ out)
{
    extern __shared__ float sm[];
    float* xs  = sm;                         // ROWS*XSTRIDE          (8320 f)
    float* sel = xs + ROWS * XSTRIDE;        // LANES*DD*FF           (12288 f)
    float* red = sel + LANES * DD * FF;      // LANES*ROWS*REDSTR     (4352 f)

    const int tid = threadIdx.x;
    const int row = tid & 31;                // lane -> batch row
    const int wid = tid >> 5;                // warp -> tree
    const int b0  = blockIdx.x * ROWS;
    const int t0  = blockIdx.y * TPB;
    const int t   = t0 + wid;

    // stage x tile (coalesced gmem -> padded smem)
    for (int i = tid; i < ROWS * (FF / 4); i += THREADS) {
        int r = i >> 6, c4 = i & 63;
        float4 v = reinterpret_cast<const float4*>(x + (size_t)(b0 + r) * FF)[c4];
        *reinterpret_cast<float4*>(xs + r * XSTRIDE + 4 * c4) = v;
    }
    // stage selectors for this block's 8 trees (contiguous slab)
    {
        const float4* ssrc = reinterpret_cast<const float4*>(
            g_selW + (size_t)t0 * DD * FF);
        float4* sdst = reinterpret_cast<float4*>(sel);
        for (int i = tid; i < LANES * DD * FF / 4; i += THREADS) sdst[i] = ssrc[i];
    }

    // per-tree sparsemoid affine (uniform loads, register-resident)
    float ra[DD], rb[DD];
#pragma unroll
    for (int d = 0; d < DD; ++d) {
        ra[d] = __ldg(g_a + t * DD + d);
        rb[d] = __ldg(g_b + t * DD + d);
    }
    __syncthreads();

    const float*      selT = sel + wid * DD * FF;
    const ulonglong2* xr2  = reinterpret_cast<const ulonglong2*>(xs + row * XSTRIDE);

    // fv[d] = x_row . sel[d]  -- 12 independent packed FMA chains
    u64t pa[DD], pb[DD];
#pragma unroll
    for (int d = 0; d < DD; ++d) { pa[d] = 0ULL; pb[d] = 0ULL; }
#pragma unroll 4
    for (int k4 = 0; k4 < FF / 4; ++k4) {
        ulonglong2 xv = xr2[k4];
#pragma unroll
        for (int d = 0; d < DD; ++d) {
            ulonglong2 sv = reinterpret_cast<const ulonglong2*>(selT + d * FF)[k4];
            pa[d] = ffma2(xv.x, sv.x, pa[d]);
            pb[d] = ffma2(xv.y, sv.y, pb[d]);
        }
    }

    // sparsemoid: s = clamp(fv*a + b, 0, 1)
    float s[DD];
#pragma unroll
    for (int d = 0; d < DD; ++d) {
        float2 va = unpk2(pa[d]);
        float2 vb = unpk2(pb[d]);
        float fv = (va.x + va.y) + (vb.x + vb.y);
        s[d] = __saturatef(fv * ra[d] + rb[d]);
    }

    // product tree over depths 1..5 -> v[32]; depth 0 folds into packed pairs:
    // leaf {2j, 2j+1} = v[j] * (s0, 1-s0)
    float v[NBIN / 2];
    v[0] = s[1];
    v[1] = 1.0f - s[1];
#pragma unroll
    for (int d = 2; d < DD; ++d) {
#pragma unroll
        for (int c = 0; c < (1 << (d - 1)); ++c) {
            float lo = v[c];
            v[c] = lo * s[d];
            v[c + (1 << (d - 1))] = lo * (1.0f - s[d]);
        }
    }
    const u64t s0pair = pk2(s[0], 1.0f - s[0]);

    // response contraction, bin-halved to cap live registers (~16 u64 w2 alive)
    float* redp = red + (wid * ROWS + row) * REDSTR;
    const ulonglong2* rbase =
        reinterpret_cast<const ulonglong2*>(resp + (size_t)t * UU * NBIN);

#pragma unroll
    for (int h = 0; h < 2; ++h) {
        u64t w2[16];
#pragma unroll
        for (int j = 0; j < 16; ++j) {
            float vv = v[16 * h + j];
            w2[j] = fmul2(pk2(vv, vv), s0pair);
        }
#pragma unroll
        for (int u = 0; u < UU; ++u) {
            const ulonglong2* rr = rbase + u * (NBIN / 4) + 8 * h;
            u64t ca = 0ULL, cb = 0ULL;
#pragma unroll
            for (int q = 0; q < 8; ++q) {
                ulonglong2 rv = __ldg(rr + q);
                ca = ffma2(w2[2 * q + 0], rv.x, ca);
                cb = ffma2(w2[2 * q + 1], rv.y, cb);
            }
            float2 a2 = unpk2(ca);
            float2 b2 = unpk2(cb);
            float sum = (a2.x + a2.y) + (b2.x + b2.y);
            if (h == 0) redp[u] = sum;
            else        redp[u] += sum;
        }
    }
    __syncthreads();

    // reduce 8 warp-slabs -> global atomic accumulation (tree-split across y)
    for (int i = tid; i < ROWS * UU; i += THREADS) {
        int r = i >> 4, u = i & 15;
        float ssum = 0.f;
#pragma unroll
        for (int w = 0; w < LANES; ++w)
            ssum += red[(w * ROWS + r) * REDSTR + u];
        atomicAdd(&out[(size_t)(b0 + r) * UU + u], ssum);
    }
}

// ---------------------------------------------------------------------------
extern "C" void kernel_launch(void* const* d_in, const int* in_sizes, int n_in,
                              void* d_out, int out_size)
{
    const float* x    = (const float*)d_in[0];
    const float* fsl  = (const float*)d_in[1];
    const float* th   = (const float*)d_in[2];
    const float* lt   = (const float*)d_in[3];
    const float* resp = (const float*)d_in[4];
    float* out = (float*)d_out;

    cudaMemsetAsync(out, 0, (size_t)out_size * sizeof(float));

    prep_kernel<<<(FF * TT + 255) / 256, 256>>>(fsl, th, lt);

    const int smem = (ROWS * XSTRIDE + LANES * DD * FF + LANES * ROWS * REDSTR)
                     * (int)sizeof(float);
    cudaFuncSetAttribute(main_kernel, cudaFuncAttributeMaxDynamicSharedMemorySize, smem);
    main_kernel<<<dim3(BB / ROWS, TSPLIT), THREADS, smem>>>(x, resp, out);
}

// round 7
// speedup vs baseline: 1.2918x; 1.2918x over previous
#include <cuda_runtime.h>

#define BB 4096
#define FF 256
#define TT 128
#define DD 6
#define UU 16
#define NBIN 64

#define ROWS 64           /* batch rows per CTA (2 per thread-lane) */
#define LANES 8           /* trees per CTA = warps per CTA */
#define THREADS 256
#define TSPLIT 16
#define TPB (TT / TSPLIT) /* 8 trees per block, one group, no loop */
#define XSTRIDE 260       /* 256+4 pad: conflict-free LDS.128 across rows */
#define REDSTR 17         /* padded stride for per-warp reduction slab */

typedef unsigned long long u64t;

// ---- packed f32x2 helpers (sm_103a FFMA2 path, PTX-only per SASS_QUICKREF) ----
__device__ __forceinline__ u64t ffma2(u64t a, u64t b, u64t c) {
    u64t d;
    asm("fma.rn.f32x2 %0, %1, %2, %3;" : "=l"(d) : "l"(a), "l"(b), "l"(c));
    return d;
}
__device__ __forceinline__ u64t fmul2(u64t a, u64t b) {
    u64t d;
    asm("mul.rn.f32x2 %0, %1, %2;" : "=l"(d) : "l"(a), "l"(b));
    return d;
}
__device__ __forceinline__ u64t pk2(float lo, float hi) {
    u64t p;
    asm("mov.b64 %0, {%1, %2};" : "=l"(p) : "f"(lo), "f"(hi));
    return p;
}
__device__ __forceinline__ float2 unpk2(u64t p) {
    float2 v;
    asm("mov.b64 {%0, %1}, %2;" : "=f"(v.x), "=f"(v.y) : "l"(p));
    return v;
}

// Scratch (device globals: no runtime allocation allowed)
__device__ __align__(16) float g_selW[TT * DD * FF];   // [t][d][f], sparsemax-ed selectors
__device__ __align__(16) float g_a[TT * DD];           // 0.5*exp(-lt)
__device__ __align__(16) float g_b[TT * DD];           // 0.5 - th*a

// ---------------------------------------------------------------------------
// Prep: sparsemax over D=6 per (f,t); also the per-(t,d) affine for sparsemoid
// ---------------------------------------------------------------------------
__global__ void prep_kernel(const float* __restrict__ fsl,
                            const float* __restrict__ th,
                            const float* __restrict__ lt)
{
    int n = blockIdx.x * blockDim.x + threadIdx.x;

    if (n < TT * DD) {
        float a = 0.5f * expf(-lt[n]);
        g_a[n] = a;
        g_b[n] = 0.5f - th[n] * a;
    }
    if (n >= FF * TT) return;

    int f = n / TT;
    int t = n - f * TT;

    const float* zp = fsl + (size_t)f * (TT * DD) + t * DD;
    float z[DD], zs[DD];
#pragma unroll
    for (int d = 0; d < DD; ++d) { z[d] = zp[d]; zs[d] = z[d]; }

    // descending bubble sorting network (15 comparators, D=6)
#pragma unroll
    for (int p = 0; p < DD - 1; ++p) {
#pragma unroll
        for (int i = 0; i < DD - 1 - p; ++i) {
            float mx = fmaxf(zs[i], zs[i + 1]);
            float mn = fminf(zs[i], zs[i + 1]);
            zs[i] = mx; zs[i + 1] = mn;
        }
    }

    // sparsemax threshold
    float cs = 0.f, css = 0.f;
    int kz = 0;
#pragma unroll
    for (int k = 1; k <= DD; ++k) {
        cs += zs[k - 1];
        if (1.0f + (float)k * zs[k - 1] > cs) { kz = k; css = cs; }
    }
    float tau = (css - 1.0f) / (float)kz;

#pragma unroll
    for (int d = 0; d < DD; ++d)
        g_selW[(size_t)(t * DD + d) * FF + f] = fmaxf(z[d] - tau, 0.0f);
}

// ---------------------------------------------------------------------------
// Fused main kernel. warp <-> tree; each lane owns TWO batch rows (l, l+32).
// 1 CTA/SM, no register cap (no spills). resp via uniform __ldg (L1D).
// ---------------------------------------------------------------------------
__global__ void __launch_bounds__(THREADS)
main_kernel(const float* __restrict__ x,
            const float* __restrict__ resp,
            float* __restrict__ out)
{
    extern __shared__ float sm[];
    float* xs  = sm;                         // ROWS*XSTRIDE          (16640 f)
    float* sel = xs + ROWS * XSTRIDE;        // LANES*DD*FF           (12288 f)
    float* red = sel + LANES * DD * FF;      // LANES*ROWS*REDSTR     (8704 f)

    const int tid  = threadIdx.x;
    const int lane = tid & 31;
    const int wid  = tid >> 5;               // warp -> tree
    const int rA   = lane;                   // row A
    const int rB   = lane + 32;              // row B
    const int b0   = blockIdx.x * ROWS;
    const int t0   = blockIdx.y * TPB;
    const int t    = t0 + wid;

    // stage x tile (coalesced gmem -> padded smem), 64 rows
    for (int i = tid; i < ROWS * (FF / 4); i += THREADS) {
        int r = i >> 6, c4 = i & 63;
        float4 v = reinterpret_cast<const float4*>(x + (size_t)(b0 + r) * FF)[c4];
        *reinterpret_cast<float4*>(xs + r * XSTRIDE + 4 * c4) = v;
    }
    // stage selectors for this block's 8 trees (contiguous slab)
    {
        const float4* ssrc = reinterpret_cast<const float4*>(
            g_selW + (size_t)t0 * DD * FF);
        float4* sdst = reinterpret_cast<float4*>(sel);
        for (int i = tid; i < LANES * DD * FF / 4; i += THREADS) sdst[i] = ssrc[i];
    }

    // per-tree sparsemoid affine (uniform loads, register-resident)
    float ra[DD], rb[DD];
#pragma unroll
    for (int d = 0; d < DD; ++d) {
        ra[d] = __ldg(g_a + t * DD + d);
        rb[d] = __ldg(g_b + t * DD + d);
    }
    __syncthreads();

    const float*      selT = sel + wid * DD * FF;
    const ulonglong2* xrA  = reinterpret_cast<const ulonglong2*>(xs + rA * XSTRIDE);
    const ulonglong2* xrB  = reinterpret_cast<const ulonglong2*>(xs + rB * XSTRIDE);

    // fv[d] for both rows: 24 independent packed FMA chains, shared sel loads
    u64t paA[DD], pbA[DD], paB[DD], pbB[DD];
#pragma unroll
    for (int d = 0; d < DD; ++d) { paA[d] = pbA[d] = paB[d] = pbB[d] = 0ULL; }
#pragma unroll 4
    for (int k4 = 0; k4 < FF / 4; ++k4) {
        ulonglong2 xvA = xrA[k4];
        ulonglong2 xvB = xrB[k4];
#pragma unroll
        for (int d = 0; d < DD; ++d) {
            ulonglong2 sv = reinterpret_cast<const ulonglong2*>(selT + d * FF)[k4];
            paA[d] = ffma2(xvA.x, sv.x, paA[d]);
            pbA[d] = ffma2(xvA.y, sv.y, pbA[d]);
            paB[d] = ffma2(xvB.x, sv.x, paB[d]);
            pbB[d] = ffma2(xvB.y, sv.y, pbB[d]);
        }
    }

    // sparsemoid for both rows
    float sA[DD], sB[DD];
#pragma unroll
    for (int d = 0; d < DD; ++d) {
        float2 vaA = unpk2(paA[d]), vbA = unpk2(pbA[d]);
        float2 vaB = unpk2(paB[d]), vbB = unpk2(pbB[d]);
        sA[d] = __saturatef(((vaA.x + vaA.y) + (vbA.x + vbA.y)) * ra[d] + rb[d]);
        sB[d] = __saturatef(((vaB.x + vaB.y) + (vbB.x + vbB.y)) * ra[d] + rb[d]);
    }

    // product trees over depths 1..5 (32 entries each); depth 0 folds packed
    float vA[NBIN / 2], vB[NBIN / 2];
    vA[0] = sA[1];  vA[1] = 1.0f - sA[1];
    vB[0] = sB[1];  vB[1] = 1.0f - sB[1];
#pragma unroll
    for (int d = 2; d < DD; ++d) {
#pragma unroll
        for (int c = 0; c < (1 << (d - 1)); ++c) {
            float loA = vA[c], loB = vB[c];
            vA[c] = loA * sA[d];
            vA[c + (1 << (d - 1))] = loA * (1.0f - sA[d]);
            vB[c] = loB * sB[d];
            vB[c + (1 << (d - 1))] = loB * (1.0f - sB[d]);
        }
    }
    const u64t s0A = pk2(sA[0], 1.0f - sA[0]);
    const u64t s0B = pk2(sB[0], 1.0f - sB[0]);

    // response contraction: both rows share each resp load. Halved over bins
    // to bound live registers (wA/wB = 32 u64 per half).
    float* redA = red + (wid * ROWS + rA) * REDSTR;
    float* redB = red + (wid * ROWS + rB) * REDSTR;
    const ulonglong2* rbase =
        reinterpret_cast<const ulonglong2*>(resp + (size_t)t * UU * NBIN);

#pragma unroll
    for (int h = 0; h < 2; ++h) {
        u64t wA[16], wB[16];
#pragma unroll
        for (int j = 0; j < 16; ++j) {
            float va = vA[16 * h + j], vb = vB[16 * h + j];
            wA[j] = fmul2(pk2(va, va), s0A);
            wB[j] = fmul2(pk2(vb, vb), s0B);
        }
#pragma unroll
        for (int u = 0; u < UU; ++u) {
            const ulonglong2* rr = rbase + u * (NBIN / 4) + 8 * h;
            u64t cA0 = 0ULL, cA1 = 0ULL, cB0 = 0ULL, cB1 = 0ULL;
#pragma unroll
            for (int q = 0; q < 8; ++q) {
                ulonglong2 rv = __ldg(rr + q);
                cA0 = ffma2(wA[2 * q + 0], rv.x, cA0);
                cA1 = ffma2(wA[2 * q + 1], rv.y, cA1);
                cB0 = ffma2(wB[2 * q + 0], rv.x, cB0);
                cB1 = ffma2(wB[2 * q + 1], rv.y, cB1);
            }
            float2 a0 = unpk2(cA0), a1 = unpk2(cA1);
            float2 b0v = unpk2(cB0), b1v = unpk2(cB1);
            float sumA = (a0.x + a0.y) + (a1.x + a1.y);
            float sumB = (b0v.x + b0v.y) + (b1v.x + b1v.y);
            if (h == 0) { redA[u] = sumA;  redB[u] = sumB; }
            else        { redA[u] += sumA; redB[u] += sumB; }
        }
    }
    __syncthreads();

    // reduce 8 warp-slabs -> global atomic accumulation (tree-split across y)
    for (int i = tid; i < ROWS * UU; i += THREADS) {
        int r = i >> 4, u = i & 15;
        float ssum = 0.f;
#pragma unroll
        for (int w = 0; w < LANES; ++w)
            ssum += red[(w * ROWS + r) * REDSTR + u];
        atomicAdd(&out[(size_t)(b0 + r) * UU + u], ssum);
    }
}

// ---------------------------------------------------------------------------
extern "C" void kernel_launch(void* const* d_in, const int* in_sizes, int n_in,
                              void* d_out, int out_size)
{
    const float* x    = (const float*)d_in[0];
    const float* fsl  = (const float*)d_in[1];
    const float* th   = (const float*)d_in[2];
    const float* lt   = (const float*)d_in[3];
    const float* resp = (const float*)d_in[4];
    float* out = (float*)d_out;

    cudaMemsetAsync(out, 0, (size_t)out_size * sizeof(float));

    prep_kernel<<<(FF * TT + 255) / 256, 256>>>(fsl, th, lt);

    const int smem = (ROWS * XSTRIDE + LANES * DD * FF + LANES * ROWS * REDSTR)
                     * (int)sizeof(float);
    cudaFuncSetAttribute(main_kernel, cudaFuncAttributeMaxDynamicSharedMemorySize, smem);
    main_kernel<<<dim3(BB / ROWS, TSPLIT), THREADS, smem>>>(x, resp, out);
}

// round 10
// speedup vs baseline: 1.9350x; 1.4980x over previous
#include <cuda_runtime.h>

#define BB 4096
#define FF 256
#define TT 128
#define DD 6
#define UU 16
#define NBIN 64

#define ROWS 64           /* batch rows per CTA (2 per thread-lane) */
#define LANES 8           /* trees per CTA = warps per CTA */
#define THREADS 256
#define TSPLIT 16
#define TPB (TT / TSPLIT) /* 8 trees per block, one group, no loop */
#define XSTRIDE 260       /* 256+4 pad: conflict-free LDS.128 across rows */
#define REDSTR 17         /* padded stride for per-warp reduction slab */

typedef unsigned long long u64t;

// ---- packed f32x2 helpers (sm_103a FFMA2 path, PTX-only per SASS_QUICKREF) ----
__device__ __forceinline__ u64t ffma2(u64t a, u64t b, u64t c) {
    u64t d;
    asm("fma.rn.f32x2 %0, %1, %2, %3;" : "=l"(d) : "l"(a), "l"(b), "l"(c));
    return d;
}
__device__ __forceinline__ u64t fmul2(u64t a, u64t b) {
    u64t d;
    asm("mul.rn.f32x2 %0, %1, %2;" : "=l"(d) : "l"(a), "l"(b));
    return d;
}
__device__ __forceinline__ u64t pk2(float lo, float hi) {
    u64t p;
    asm("mov.b64 %0, {%1, %2};" : "=l"(p) : "f"(lo), "f"(hi));
    return p;
}
__device__ __forceinline__ float2 unpk2(u64t p) {
    float2 v;
    asm("mov.b64 {%0, %1}, %2;" : "=f"(v.x), "=f"(v.y) : "l"(p));
    return v;
}

// Scratch (device globals: no runtime allocation allowed)
__device__ __align__(16) float g_selW[TT * DD * FF];   // [t][d][f], sparsemax-ed selectors
__device__ __align__(16) float g_a[TT * DD];           // 0.5*exp(-lt)
__device__ __align__(16) float g_b[TT * DD];           // 0.5 - th*a

// ---------------------------------------------------------------------------
// Prep: sparsemax over D=6 per (f,t); also the per-(t,d) affine for sparsemoid
// ---------------------------------------------------------------------------
__global__ void prep_kernel(const float* __restrict__ fsl,
                            const float* __restrict__ th,
                            const float* __restrict__ lt)
{
    int n = blockIdx.x * blockDim.x + threadIdx.x;

    if (n < TT * DD) {
        float a = 0.5f * expf(-lt[n]);
        g_a[n] = a;
        g_b[n] = 0.5f - th[n] * a;
    }
    if (n >= FF * TT) return;

    int f = n / TT;
    int t = n - f * TT;

    const float* zp = fsl + (size_t)f * (TT * DD) + t * DD;
    float z[DD], zs[DD];
#pragma unroll
    for (int d = 0; d < DD; ++d) { z[d] = zp[d]; zs[d] = z[d]; }

    // descending bubble sorting network (15 comparators, D=6)
#pragma unroll
    for (int p = 0; p < DD - 1; ++p) {
#pragma unroll
        for (int i = 0; i < DD - 1 - p; ++i) {
            float mx = fmaxf(zs[i], zs[i + 1]);
            float mn = fminf(zs[i], zs[i + 1]);
            zs[i] = mx; zs[i + 1] = mn;
        }
    }

    // sparsemax threshold
    float cs = 0.f, css = 0.f;
    int kz = 0;
#pragma unroll
    for (int k = 1; k <= DD; ++k) {
        cs += zs[k - 1];
        if (1.0f + (float)k * zs[k - 1] > cs) { kz = k; css = cs; }
    }
    float tau = (css - 1.0f) / (float)kz;

#pragma unroll
    for (int d = 0; d < DD; ++d)
        g_selW[(size_t)(t * DD + d) * FF + f] = fmaxf(z[d] - tau, 0.0f);
}

// ---------------------------------------------------------------------------
// Fused main kernel. warp <-> tree; each lane owns TWO batch rows (l, l+32).
// 2 CTAs/SM: smem = x tile + reduction slab only (~99KB); sel and resp are
// warp-uniform __ldg. Epilogue in bin-quarters to keep live regs < 128.
// ---------------------------------------------------------------------------
__global__ void __launch_bounds__(THREADS, 2)
main_kernel(const float* __restrict__ x,
            const float* __restrict__ resp,
            float* __restrict__ out)
{
    extern __shared__ float sm[];
    float* xs  = sm;                         // ROWS*XSTRIDE          (16640 f)
    float* red = xs + ROWS * XSTRIDE;        // LANES*ROWS*REDSTR     (8704 f)

    const int tid  = threadIdx.x;
    const int lane = tid & 31;
    const int wid  = tid >> 5;               // warp -> tree
    const int rA   = lane;                   // row A
    const int rB   = lane + 32;              // row B
    const int b0   = blockIdx.x * ROWS;
    const int t0   = blockIdx.y * TPB;
    const int t    = t0 + wid;

    // stage x tile (coalesced gmem -> padded smem), 64 rows
    for (int i = tid; i < ROWS * (FF / 4); i += THREADS) {
        int r = i >> 6, c4 = i & 63;
        float4 v = reinterpret_cast<const float4*>(x + (size_t)(b0 + r) * FF)[c4];
        *reinterpret_cast<float4*>(xs + r * XSTRIDE + 4 * c4) = v;
    }

    // per-tree sparsemoid affine (uniform loads, register-resident)
    float ra[DD], rb[DD];
#pragma unroll
    for (int d = 0; d < DD; ++d) {
        ra[d] = __ldg(g_a + t * DD + d);
        rb[d] = __ldg(g_b + t * DD + d);
    }
    __syncthreads();

    const ulonglong2* selG =
        reinterpret_cast<const ulonglong2*>(g_selW + (size_t)t * DD * FF);
    const ulonglong2* xrA = reinterpret_cast<const ulonglong2*>(xs + rA * XSTRIDE);
    const ulonglong2* xrB = reinterpret_cast<const ulonglong2*>(xs + rB * XSTRIDE);

    // fv[d] for both rows: 24 packed FMA chains; sel via uniform LDG (1 wf each)
    u64t paA[DD], pbA[DD], paB[DD], pbB[DD];
#pragma unroll
    for (int d = 0; d < DD; ++d) { paA[d] = pbA[d] = paB[d] = pbB[d] = 0ULL; }
#pragma unroll 4
    for (int k4 = 0; k4 < FF / 4; ++k4) {
        ulonglong2 xvA = xrA[k4];
        ulonglong2 xvB = xrB[k4];
#pragma unroll
        for (int d = 0; d < DD; ++d) {
            ulonglong2 sv = __ldg(selG + d * (FF / 4) + k4);
            paA[d] = ffma2(xvA.x, sv.x, paA[d]);
            pbA[d] = ffma2(xvA.y, sv.y, pbA[d]);
            paB[d] = ffma2(xvB.x, sv.x, paB[d]);
            pbB[d] = ffma2(xvB.y, sv.y, pbB[d]);
        }
    }

    // sparsemoid for both rows
    float sA[DD], sB[DD];
#pragma unroll
    for (int d = 0; d < DD; ++d) {
        float2 vaA = unpk2(paA[d]), vbA = unpk2(pbA[d]);
        float2 vaB = unpk2(paB[d]), vbB = unpk2(pbB[d]);
        sA[d] = __saturatef(((vaA.x + vaA.y) + (vbA.x + vbA.y)) * ra[d] + rb[d]);
        sB[d] = __saturatef(((vaB.x + vaB.y) + (vbB.x + vbB.y)) * ra[d] + rb[d]);
    }

    // shared subtree over bits 1..3 (8 entries per row); bits 4,5 become the
    // per-quarter scalar, bit 0 the packed pair.
    float v8A[8], v8B[8];
    v8A[0] = sA[1];  v8A[1] = 1.0f - sA[1];
    v8B[0] = sB[1];  v8B[1] = 1.0f - sB[1];
#pragma unroll
    for (int d = 2; d < 4; ++d) {
#pragma unroll
        for (int c = 0; c < (1 << (d - 1)); ++c) {
            float loA = v8A[c], loB = v8B[c];
            v8A[c] = loA * sA[d];
            v8A[c + (1 << (d - 1))] = loA * (1.0f - sA[d]);
            v8B[c] = loB * sB[d];
            v8B[c + (1 << (d - 1))] = loB * (1.0f - sB[d]);
        }
    }

    float* redA = red + (wid * ROWS + rA) * REDSTR;
    float* redB = red + (wid * ROWS + rB) * REDSTR;
    const ulonglong2* rbase =
        reinterpret_cast<const ulonglong2*>(resp + (size_t)t * UU * NBIN);

    // quarters over bins: h bit0 <-> s[4], h bit1 <-> s[5]
#pragma unroll
    for (int h = 0; h < 4; ++h) {
        float qA = ((h & 1) ? (1.0f - sA[4]) : sA[4]) *
                   ((h & 2) ? (1.0f - sA[5]) : sA[5]);
        float qB = ((h & 1) ? (1.0f - sB[4]) : sB[4]) *
                   ((h & 2) ? (1.0f - sB[5]) : sB[5]);
        const u64t qsA = pk2(qA * sA[0], qA * (1.0f - sA[0]));
        const u64t qsB = pk2(qB * sB[0], qB * (1.0f - sB[0]));

        u64t wA[8], wB[8];
#pragma unroll
        for (int j = 0; j < 8; ++j) {
            wA[j] = fmul2(pk2(v8A[j], v8A[j]), qsA);
            wB[j] = fmul2(pk2(v8B[j], v8B[j]), qsB);
        }

#pragma unroll
        for (int u = 0; u < UU; ++u) {
            const ulonglong2* rr = rbase + u * (NBIN / 4) + 4 * h;
            u64t cA0 = 0ULL, cA1 = 0ULL, cB0 = 0ULL, cB1 = 0ULL;
#pragma unroll
            for (int q = 0; q < 4; ++q) {
                ulonglong2 rv = __ldg(rr + q);
                cA0 = ffma2(wA[2 * q + 0], rv.x, cA0);
                cA1 = ffma2(wA[2 * q + 1], rv.y, cA1);
                cB0 = ffma2(wB[2 * q + 0], rv.x, cB0);
                cB1 = ffma2(wB[2 * q + 1], rv.y, cB1);
            }
            float2 a0 = unpk2(cA0), a1 = unpk2(cA1);
            float2 b0v = unpk2(cB0), b1v = unpk2(cB1);
            float sumA = (a0.x + a0.y) + (a1.x + a1.y);
            float sumB = (b0v.x + b0v.y) + (b1v.x + b1v.y);
            if (h == 0) { redA[u] = sumA;  redB[u] = sumB; }
            else        { redA[u] += sumA; redB[u] += sumB; }
        }
    }
    __syncthreads();

    // reduce 8 warp-slabs -> global atomic accumulation (tree-split across y)
    for (int i = tid; i < ROWS * UU; i += THREADS) {
        int r = i >> 4, u = i & 15;
        float ssum = 0.f;
#pragma unroll
        for (int w = 0; w < LANES; ++w)
            ssum += red[(w * ROWS + r) * REDSTR + u];
        atomicAdd(&out[(size_t)(b0 + r) * UU + u], ssum);
    }
}

// ---------------------------------------------------------------------------
extern "C" void kernel_launch(void* const* d_in, const int* in_sizes, int n_in,
                              void* d_out, int out_size)
{
    const float* x    = (const float*)d_in[0];
    const float* fsl  = (const float*)d_in[1];
    const float* th   = (const float*)d_in[2];
    const float* lt   = (const float*)d_in[3];
    const float* resp = (const float*)d_in[4];
    float* out = (float*)d_out;

    cudaMemsetAsync(out, 0, (size_t)out_size * sizeof(float));

    prep_kernel<<<(FF * TT + 255) / 256, 256>>>(fsl, th, lt);

    const int smem = (ROWS * XSTRIDE + LANES * ROWS * REDSTR) * (int)sizeof(float);
    cudaFuncSetAttribute(main_kernel, cudaFuncAttributeMaxDynamicSharedMemorySize, smem);
    main_kernel<<<dim3(BB / ROWS, TSPLIT), THREADS, smem>>>(x, resp, out);
}

// round 11
// speedup vs baseline: 1.9940x; 1.0304x over previous
#include <cuda_runtime.h>

#define BB 4096
#define FF 256
#define TT 128
#define DD 6
#define UU 16
#define NBIN 64

#define ROWS 64           /* batch rows per CTA (2 per thread-lane) */
#define LANES 8           /* trees per CTA = warps per CTA */
#define THREADS 256
#define TSPLIT 16
#define TPB (TT / TSPLIT) /* 8 trees per block, one group, no loop */
#define XSTRIDE 260       /* 256+4 pad: conflict-free LDS.128 across rows */
#define REDSTR 17         /* padded stride: lane*17 covers all 32 banks */

typedef unsigned long long u64t;

// ---- packed f32x2 helpers (sm_103a FFMA2 path, PTX-only per SASS_QUICKREF) ----
__device__ __forceinline__ u64t ffma2(u64t a, u64t b, u64t c) {
    u64t d;
    asm("fma.rn.f32x2 %0, %1, %2, %3;" : "=l"(d) : "l"(a), "l"(b), "l"(c));
    return d;
}
__device__ __forceinline__ u64t fmul2(u64t a, u64t b) {
    u64t d;
    asm("mul.rn.f32x2 %0, %1, %2;" : "=l"(d) : "l"(a), "l"(b));
    return d;
}
__device__ __forceinline__ u64t pk2(float lo, float hi) {
    u64t p;
    asm("mov.b64 %0, {%1, %2};" : "=l"(p) : "f"(lo), "f"(hi));
    return p;
}
__device__ __forceinline__ float2 unpk2(u64t p) {
    float2 v;
    asm("mov.b64 {%0, %1}, %2;" : "=f"(v.x), "=f"(v.y) : "l"(p));
    return v;
}

// Scratch (device globals: no runtime allocation allowed)
__device__ __align__(16) float g_selW[TT * DD * FF];   // [t][d][f], sparsemax-ed selectors
__device__ __align__(16) float g_a[TT * DD];           // 0.5*exp(-lt)
__device__ __align__(16) float g_b[TT * DD];           // 0.5 - th*a

// ---------------------------------------------------------------------------
// Prep: sparsemax over D=6 per (f,t); also the per-(t,d) affine for sparsemoid
// ---------------------------------------------------------------------------
__global__ void prep_kernel(const float* __restrict__ fsl,
                            const float* __restrict__ th,
                            const float* __restrict__ lt)
{
    int n = blockIdx.x * blockDim.x + threadIdx.x;

    if (n < TT * DD) {
        float a = 0.5f * expf(-lt[n]);
        g_a[n] = a;
        g_b[n] = 0.5f - th[n] * a;
    }
    if (n >= FF * TT) return;

    int f = n / TT;
    int t = n - f * TT;

    const float* zp = fsl + (size_t)f * (TT * DD) + t * DD;
    float z[DD], zs[DD];
#pragma unroll
    for (int d = 0; d < DD; ++d) { z[d] = zp[d]; zs[d] = z[d]; }

    // descending bubble sorting network (15 comparators, D=6)
#pragma unroll
    for (int p = 0; p < DD - 1; ++p) {
#pragma unroll
        for (int i = 0; i < DD - 1 - p; ++i) {
            float mx = fmaxf(zs[i], zs[i + 1]);
            float mn = fminf(zs[i], zs[i + 1]);
            zs[i] = mx; zs[i + 1] = mn;
        }
    }

    // sparsemax threshold
    float cs = 0.f, css = 0.f;
    int kz = 0;
#pragma unroll
    for (int k = 1; k <= DD; ++k) {
        cs += zs[k - 1];
        if (1.0f + (float)k * zs[k - 1] > cs) { kz = k; css = cs; }
    }
    float tau = (css - 1.0f) / (float)kz;

#pragma unroll
    for (int d = 0; d < DD; ++d)
        g_selW[(size_t)(t * DD + d) * FF + f] = fmaxf(z[d] - tau, 0.0f);
}

// ---------------------------------------------------------------------------
// Fused main kernel. warp <-> tree; each lane owns TWO batch rows (l, l+32).
// 2 CTAs/SM at ~69KB smem -> ~86KB L1D carveout keeps sel+resp L1-resident.
// Epilogue accumulates in registers across quarters; single shared-atomic flush.
// ---------------------------------------------------------------------------
__global__ void __launch_bounds__(THREADS, 2)
main_kernel(const float* __restrict__ x,
            const float* __restrict__ resp,
            float* __restrict__ out)
{
    extern __shared__ float sm[];
    float* xs  = sm;                         // ROWS*XSTRIDE   (16640 f)
    float* red = xs + ROWS * XSTRIDE;        // ROWS*REDSTR    (1088 f)

    const int tid  = threadIdx.x;
    const int lane = tid & 31;
    const int wid  = tid >> 5;               // warp -> tree
    const int rA   = lane;                   // row A
    const int rB   = lane + 32;              // row B
    const int b0   = blockIdx.x * ROWS;
    const int t0   = blockIdx.y * TPB;
    const int t    = t0 + wid;

    // stage x tile (coalesced gmem -> padded smem), 64 rows
    for (int i = tid; i < ROWS * (FF / 4); i += THREADS) {
        int r = i >> 6, c4 = i & 63;
        float4 v = reinterpret_cast<const float4*>(x + (size_t)(b0 + r) * FF)[c4];
        *reinterpret_cast<float4*>(xs + r * XSTRIDE + 4 * c4) = v;
    }
    // zero reduction slab (atomic accumulation target)
    for (int i = tid; i < ROWS * REDSTR; i += THREADS) red[i] = 0.f;

    // per-tree sparsemoid affine (uniform loads, register-resident)
    float ra[DD], rb[DD];
#pragma unroll
    for (int d = 0; d < DD; ++d) {
        ra[d] = __ldg(g_a + t * DD + d);
        rb[d] = __ldg(g_b + t * DD + d);
    }
    __syncthreads();

    const ulonglong2* selG =
        reinterpret_cast<const ulonglong2*>(g_selW + (size_t)t * DD * FF);
    const ulonglong2* xrA = reinterpret_cast<const ulonglong2*>(xs + rA * XSTRIDE);
    const ulonglong2* xrB = reinterpret_cast<const ulonglong2*>(xs + rB * XSTRIDE);

    // fv[d] for both rows: 24 packed FMA chains; sel via uniform LDG (L1-resident)
    u64t paA[DD], pbA[DD], paB[DD], pbB[DD];
#pragma unroll
    for (int d = 0; d < DD; ++d) { paA[d] = pbA[d] = paB[d] = pbB[d] = 0ULL; }
#pragma unroll 8
    for (int k4 = 0; k4 < FF / 4; ++k4) {
        ulonglong2 xvA = xrA[k4];
        ulonglong2 xvB = xrB[k4];
#pragma unroll
        for (int d = 0; d < DD; ++d) {
            ulonglong2 sv = __ldg(selG + d * (FF / 4) + k4);
            paA[d] = ffma2(xvA.x, sv.x, paA[d]);
            pbA[d] = ffma2(xvA.y, sv.y, pbA[d]);
            paB[d] = ffma2(xvB.x, sv.x, paB[d]);
            pbB[d] = ffma2(xvB.y, sv.y, pbB[d]);
        }
    }

    // sparsemoid for both rows
    float sA[DD], sB[DD];
#pragma unroll
    for (int d = 0; d < DD; ++d) {
        float2 vaA = unpk2(paA[d]), vbA = unpk2(pbA[d]);
        float2 vaB = unpk2(paB[d]), vbB = unpk2(pbB[d]);
        sA[d] = __saturatef(((vaA.x + vaA.y) + (vbA.x + vbA.y)) * ra[d] + rb[d]);
        sB[d] = __saturatef(((vaB.x + vaB.y) + (vbB.x + vbB.y)) * ra[d] + rb[d]);
    }

    // shared subtree over bits 1..3 (8 entries per row); bits 4,5 become the
    // per-quarter scalar, bit 0 the packed pair.
    float v8A[8], v8B[8];
    v8A[0] = sA[1];  v8A[1] = 1.0f - sA[1];
    v8B[0] = sB[1];  v8B[1] = 1.0f - sB[1];
#pragma unroll
    for (int d = 2; d < 4; ++d) {
#pragma unroll
        for (int c = 0; c < (1 << (d - 1)); ++c) {
            float loA = v8A[c], loB = v8B[c];
            v8A[c] = loA * sA[d];
            v8A[c + (1 << (d - 1))] = loA * (1.0f - sA[d]);
            v8B[c] = loB * sB[d];
            v8B[c + (1 << (d - 1))] = loB * (1.0f - sB[d]);
        }
    }

    const ulonglong2* rbase =
        reinterpret_cast<const ulonglong2*>(resp + (size_t)t * UU * NBIN);

    // register accumulators across the 4 bin-quarters
    float accA[UU], accB[UU];
#pragma unroll
    for (int u = 0; u < UU; ++u) { accA[u] = 0.f; accB[u] = 0.f; }

    // quarters over bins: h bit0 <-> s[4], h bit1 <-> s[5]
#pragma unroll
    for (int h = 0; h < 4; ++h) {
        float qA = ((h & 1) ? (1.0f - sA[4]) : sA[4]) *
                   ((h & 2) ? (1.0f - sA[5]) : sA[5]);
        float qB = ((h & 1) ? (1.0f - sB[4]) : sB[4]) *
                   ((h & 2) ? (1.0f - sB[5]) : sB[5]);
        const u64t qsA = pk2(qA * sA[0], qA * (1.0f - sA[0]));
        const u64t qsB = pk2(qB * sB[0], qB * (1.0f - sB[0]));

        u64t wA[8], wB[8];
#pragma unroll
        for (int j = 0; j < 8; ++j) {
            wA[j] = fmul2(pk2(v8A[j], v8A[j]), qsA);
            wB[j] = fmul2(pk2(v8B[j], v8B[j]), qsB);
        }

#pragma unroll
        for (int u = 0; u < UU; ++u) {
            const ulonglong2* rr = rbase + u * (NBIN / 4) + 4 * h;
            u64t cA0 = 0ULL, cA1 = 0ULL, cB0 = 0ULL, cB1 = 0ULL;
#pragma unroll
            for (int q = 0; q < 4; ++q) {
                ulonglong2 rv = __ldg(rr + q);
                cA0 = ffma2(wA[2 * q + 0], rv.x, cA0);
                cA1 = ffma2(wA[2 * q + 1], rv.y, cA1);
                cB0 = ffma2(wB[2 * q + 0], rv.x, cB0);
                cB1 = ffma2(wB[2 * q + 1], rv.y, cB1);
            }
            float2 a0 = unpk2(cA0), a1 = unpk2(cA1);
            float2 b0v = unpk2(cB0), b1v = unpk2(cB1);
            accA[u] += (a0.x + a0.y) + (a1.x + a1.y);
            accB[u] += (b0v.x + b0v.y) + (b1v.x + b1v.y);
        }
    }

    // single flush: shared atomics, stride-17 slab (conflict-free lane spread)
#pragma unroll
    for (int u = 0; u < UU; ++u) {
        atomicAdd(&red[rA * REDSTR + u], accA[u]);
        atomicAdd(&red[rB * REDSTR + u], accB[u]);
    }
    __syncthreads();

    // CTA result -> global atomic accumulation (tree-split across y)
    for (int i = tid; i < ROWS * UU; i += THREADS) {
        int r = i >> 4, u = i & 15;
        atomicAdd(&out[(size_t)(b0 + r) * UU + u], red[r * REDSTR + u]);
    }
}

// ---------------------------------------------------------------------------
extern "C" void kernel_launch(void* const* d_in, const int* in_sizes, int n_in,
                              void* d_out, int out_size)
{
    const float* x    = (const float*)d_in[0];
    const float* fsl  = (const float*)d_in[1];
    const float* th   = (const float*)d_in[2];
    const float* lt   = (const float*)d_in[3];
    const float* resp = (const float*)d_in[4];
    float* out = (float*)d_out;

    cudaMemsetAsync(out, 0, (size_t)out_size * sizeof(float));

    prep_kernel<<<(FF * TT + 255) / 256, 256>>>(fsl, th, lt);

    const int smem = (ROWS * XSTRIDE + ROWS * REDSTR) * (int)sizeof(float);
    cudaFuncSetAttribute(main_kernel, cudaFuncAttributeMaxDynamicSharedMemorySize, smem);
    main_kernel<<<dim3(BB / ROWS, TSPLIT), THREADS, smem>>>(x, resp, out);
}